// round 9
// baseline (speedup 1.0000x reference)
#include <cuda_runtime.h>
#include <cstdint>

#define Bn 1024
#define Nn 64
#define Cn 256
#define Hn 8
#define On 64
#define HOn 512

#define THREADS 384
#define NPROD 256
#define XS_STRIDE 260
#define TS 68
#define CK 64                 // K-chunk for staged weights
#define UNITS_PER_HEAD 12     // 3 mats x 4 chunks
#define TOTAL_UNITS (Hn * UNITS_PER_HEAD)

// named barrier ids
#define BAR_READY0 1   // +p : producers arrive, consumers sync (384)
#define BAR_FREE0  3   // +p : consumers arrive, producers sync (384)
#define BAR_PROD   5   // producers only (256)
#define BAR_CONS   6   // consumers only (128)

#define NB_SYNC(id, cnt)   asm volatile("bar.sync %0, %1;"   :: "r"(id), "r"(cnt) : "memory")
#define NB_ARRIVE(id, cnt) asm volatile("bar.arrive %0, %1;" :: "r"(id), "r"(cnt) : "memory")

typedef unsigned long long ull;

// ---------- f32x2 packed-FMA helpers ----------
__device__ __forceinline__ ull fma2(ull a, ull b, ull c) {
    ull d;
    asm("fma.rn.f32x2 %0, %1, %2, %3;" : "=l"(d) : "l"(a), "l"(b), "l"(c));
    return d;
}
__device__ __forceinline__ ull pack2(float x) {
    ull d;
    asm("mov.b64 %0, {%1, %1};" : "=l"(d) : "f"(x));
    return d;
}
__device__ __forceinline__ ull packxy(float x, float y) {
    ull d;
    asm("mov.b64 %0, {%1, %2};" : "=l"(d) : "f"(x), "f"(y));
    return d;
}
__device__ __forceinline__ float2 unpack2(ull v) {
    float2 r;
    asm("mov.b64 {%0, %1}, %2;" : "=f"(r.x), "=f"(r.y) : "l"(v));
    return r;
}

// ---------- transposed-weight scratch ----------
__device__ __align__(16) float g_WqT[Cn * HOn];
__device__ __align__(16) float g_WkT[Cn * HOn];
__device__ __align__(16) float g_WvT[Cn * HOn];
__device__ __align__(16) float g_WsT[Cn * On];

__global__ void transpose_weights_kernel(const float* __restrict__ Wq,
                                         const float* __restrict__ Wk,
                                         const float* __restrict__ Wv,
                                         const float* __restrict__ Ws) {
    int idx = blockIdx.x * 256 + threadIdx.x;
    if (idx < Cn * HOn) {
        int c = idx / HOn, ho = idx - c * HOn;
        g_WqT[idx] = Wq[ho * Cn + c];
        g_WkT[idx] = Wk[ho * Cn + c];
        g_WvT[idx] = Wv[ho * Cn + c];
    }
    if (idx < Cn * On) {
        int c = idx / On, o = idx - c * On;
        g_WsT[idx] = Ws[o * Cn + c];
    }
}

// ---------- shared-memory layout ----------
struct __align__(16) Smem {
    float xs[Nn][XS_STRIDE];    // x row-major [i][c]
    float qs[2][Nn][TS];        // q row-major [i][o], double-buffered
    float kT[2][Nn][TS];        // k transposed [o][j]
    float vs[2][Nn][TS];        // v row-major [j][o]
    float sc[Nn][TS];           // consumer scratch: scores -> alpha
    float wbuf[2][CK][On];      // double-buffered staged weight chunk
};

__device__ __forceinline__ uint32_t smem_addr_of(const void* p) {
    uint32_t a;
    asm("{ .reg .u64 t; cvta.to.shared.u64 t, %1; cvt.u32.u64 %0, t; }"
        : "=r"(a) : "l"(p));
    return a;
}

// Stage one (head, unit) weight chunk [CK x 64] into wbuf[buf]. Producers only.
// unit u: mat = u/4 (0=Q,1=K,2=V), kc = u%4.
__device__ __forceinline__ void stage_unit(Smem& s, int buf, int h, int u, int tp) {
    int m = u >> 2, kc = u & 3;
    const float* base = (m == 0) ? g_WqT : (m == 1) ? g_WkT : g_WvT;
    const int c0 = kc * CK;
#pragma unroll
    for (int i = 0; i < 4; i++) {
        int p = tp + i * NPROD;          // 0..1023
        int kl = p >> 4, c4 = p & 15;
        const float* src = base + (size_t)(c0 + kl) * HOn + h * On + c4 * 4;
        uint32_t sa = smem_addr_of(&s.wbuf[buf][kl][c4 * 4]);
        asm volatile("cp.async.cg.shared.global [%0], [%1], 16;" :: "r"(sa), "l"(src));
    }
    asm volatile("cp.async.commit_group;");
}
#define CP_WAIT0() asm volatile("cp.async.wait_group 0;" ::: "memory")

// consumer skip GEMM: 4 rows x 8 cols tile, weights via LDG (once per CTA)
__device__ __forceinline__ void gemm48(const float* __restrict__ xrow,
                                       const float* __restrict__ wcol,
                                       ull acc[4][4]) {
#pragma unroll
    for (int a = 0; a < 4; a++)
#pragma unroll
        for (int u = 0; u < 4; u++) acc[a][u] = 0ull;
#pragma unroll 2
    for (int c4 = 0; c4 < Cn / 4; c4++) {
        float4 xv[4];
#pragma unroll
        for (int a = 0; a < 4; a++)
            xv[a] = *reinterpret_cast<const float4*>(xrow + a * XS_STRIDE + c4 * 4);
        ulonglong2 wv[4][2];
#pragma unroll
        for (int cc = 0; cc < 4; cc++) {
            const float* wp = wcol + (c4 * 4 + cc) * On;
            wv[cc][0] = *reinterpret_cast<const ulonglong2*>(wp);
            wv[cc][1] = *reinterpret_cast<const ulonglong2*>(wp + 4);
        }
#pragma unroll
        for (int cc = 0; cc < 4; cc++) {
#pragma unroll
            for (int a = 0; a < 4; a++) {
                ull xp = pack2(reinterpret_cast<const float*>(&xv[a])[cc]);
                acc[a][0] = fma2(xp, wv[cc][0].x, acc[a][0]);
                acc[a][1] = fma2(xp, wv[cc][0].y, acc[a][1]);
                acc[a][2] = fma2(xp, wv[cc][1].x, acc[a][2]);
                acc[a][3] = fma2(xp, wv[cc][1].y, acc[a][3]);
            }
        }
    }
}

__global__ void __launch_bounds__(THREADS, 1)
graph_attn_kernel(const float* __restrict__ ctx,
                  const float* __restrict__ bq, const float* __restrict__ bk,
                  const float* __restrict__ bv, const float* __restrict__ We,
                  const float* __restrict__ bs, float* __restrict__ outg) {
    extern __shared__ char smem_raw[];
    Smem& s = *reinterpret_cast<Smem*>(smem_raw);

    const int b = blockIdx.x;
    const int tid = (int)threadIdx.x;
    const bool is_prod = tid < NPROD;

    // ---- producers prefetch first weight unit before x load ----
    if (is_prod) stage_unit(s, 0, 0, 0, tid);

    // ---- all threads load x (64x256) into SMEM ----
    {
        const float4* xg = reinterpret_cast<const float4*>(ctx + (size_t)b * Nn * Cn);
        for (int p = tid; p < 4096; p += THREADS) {
            int i = p >> 6, c4 = p & 63;
            *reinterpret_cast<float4*>(&s.xs[i][c4 * 4]) = xg[p];
        }
    }
    if (is_prod) CP_WAIT0();
    __syncthreads();

    if (is_prod) {
        // ======================= PRODUCER =======================
        const int ti = tid >> 4, to = tid & 15;
        const int i0 = ti * 4, o0 = to * 4;

        for (int h = 0; h < Hn; h++) {
            const int p = h & 1;
            if (h >= 2) NB_SYNC(BAR_FREE0 + p, THREADS);

#pragma unroll 1
            for (int m = 0; m < 3; m++) {
                ull acc[4][2];
#pragma unroll
                for (int a = 0; a < 4; a++) { acc[a][0] = 0ull; acc[a][1] = 0ull; }

#pragma unroll 1
                for (int kc = 0; kc < 4; kc++) {
                    const int gu = h * UNITS_PER_HEAD + m * 4 + kc;
                    const int ngu = gu + 1;
                    if (ngu < TOTAL_UNITS)
                        stage_unit(s, ngu & 1, ngu / UNITS_PER_HEAD,
                                   ngu % UNITS_PER_HEAD, tid);

                    const float(*wb)[On] = s.wbuf[gu & 1];
                    const float* xb = &s.xs[i0][kc * CK];
#pragma unroll 8
                    for (int c4 = 0; c4 < CK / 4; c4++) {
                        float4 xv[4];
#pragma unroll
                        for (int a = 0; a < 4; a++)
                            xv[a] = *reinterpret_cast<const float4*>(
                                xb + a * XS_STRIDE + c4 * 4);
                        ulonglong2 wv[4];
#pragma unroll
                        for (int cc = 0; cc < 4; cc++)
                            wv[cc] = *reinterpret_cast<const ulonglong2*>(
                                &wb[c4 * 4 + cc][o0]);
#pragma unroll
                        for (int cc = 0; cc < 4; cc++) {
#pragma unroll
                            for (int a = 0; a < 4; a++) {
                                ull xp = pack2(reinterpret_cast<const float*>(&xv[a])[cc]);
                                acc[a][0] = fma2(xp, wv[cc].x, acc[a][0]);
                                acc[a][1] = fma2(xp, wv[cc].y, acc[a][1]);
                            }
                        }
                    }
                    CP_WAIT0();
                    NB_SYNC(BAR_PROD, NPROD);
                }

                // epilogue for mat m -> buffer p
                if (m == 0) {
                    float4 b4 = *reinterpret_cast<const float4*>(&bq[h * On + o0]);
#pragma unroll
                    for (int a = 0; a < 4; a++) {
                        float2 r0 = unpack2(acc[a][0]), r1 = unpack2(acc[a][1]);
                        float4 q = {r0.x + b4.x, r0.y + b4.y, r1.x + b4.z, r1.y + b4.w};
                        *reinterpret_cast<float4*>(&s.qs[p][i0 + a][o0]) = q;
                    }
                } else if (m == 1) {
                    float4 b4 = *reinterpret_cast<const float4*>(&bk[h * On + o0]);
                    const float bb[4] = {b4.x, b4.y, b4.z, b4.w};
#pragma unroll
                    for (int a = 0; a < 4; a++) {
                        float v[4];
                        float2 r0 = unpack2(acc[a][0]), r1 = unpack2(acc[a][1]);
                        v[0] = r0.x; v[1] = r0.y; v[2] = r1.x; v[3] = r1.y;
#pragma unroll
                        for (int c = 0; c < 4; c++)
                            s.kT[p][o0 + c][i0 + a] = v[c] + bb[c];
                    }
                } else {
                    float4 b4 = *reinterpret_cast<const float4*>(&bv[h * On + o0]);
#pragma unroll
                    for (int a = 0; a < 4; a++) {
                        float2 r0 = unpack2(acc[a][0]), r1 = unpack2(acc[a][1]);
                        float4 v = {r0.x + b4.x, r0.y + b4.y, r1.x + b4.z, r1.y + b4.w};
                        *reinterpret_cast<float4*>(&s.vs[p][i0 + a][o0]) = v;
                    }
                }
            }
            NB_ARRIVE(BAR_READY0 + p, THREADS);
        }
    } else {
        // ======================= CONSUMER =======================
        const int ct = tid - NPROD;            // 0..127
        const int it = ct >> 3, jt = ct & 7;
        const int ci0 = it * 4, co0 = jt * 8;  // 4 rows x 8 cols
        const int cw = ct >> 5, lane = ct & 31;

        // skip GEMM (overlaps head-0 projections)
        ull skacc[4][4];
        gemm48(&s.xs[ci0][0], g_WsT + co0, skacc);

        // head-sum accumulator
        ull hacc[4][4];
#pragma unroll
        for (int a = 0; a < 4; a++)
#pragma unroll
            for (int u = 0; u < 4; u++) hacc[a][u] = 0ull;

        const ull ONE = pack2(1.0f);

        for (int h = 0; h < Hn; h++) {
            const int p = h & 1;
            NB_SYNC(BAR_READY0 + p, THREADS);

            // ---- scores = q k^T / 8 (adj==1: +qe term is softmax-invariant) ----
            {
                ull sacc[4][4];
#pragma unroll
                for (int a = 0; a < 4; a++)
#pragma unroll
                    for (int u = 0; u < 4; u++) sacc[a][u] = 0ull;
#pragma unroll 4
                for (int o = 0; o < Nn; o++) {
                    ulonglong2 k0 = *reinterpret_cast<const ulonglong2*>(&s.kT[p][o][co0]);
                    ulonglong2 k1 = *reinterpret_cast<const ulonglong2*>(&s.kT[p][o][co0 + 4]);
#pragma unroll
                    for (int a = 0; a < 4; a++) {
                        ull qp = pack2(s.qs[p][ci0 + a][o]);
                        sacc[a][0] = fma2(qp, k0.x, sacc[a][0]);
                        sacc[a][1] = fma2(qp, k0.y, sacc[a][1]);
                        sacc[a][2] = fma2(qp, k1.x, sacc[a][2]);
                        sacc[a][3] = fma2(qp, k1.y, sacc[a][3]);
                    }
                }
#pragma unroll
                for (int a = 0; a < 4; a++) {
                    float2 r0 = unpack2(sacc[a][0]), r1 = unpack2(sacc[a][1]);
                    float2 r2 = unpack2(sacc[a][2]), r3 = unpack2(sacc[a][3]);
                    float4 s0 = {r0.x * 0.125f, r0.y * 0.125f, r1.x * 0.125f, r1.y * 0.125f};
                    float4 s1 = {r2.x * 0.125f, r2.y * 0.125f, r3.x * 0.125f, r3.y * 0.125f};
                    *reinterpret_cast<float4*>(&s.sc[ci0 + a][co0]) = s0;
                    *reinterpret_cast<float4*>(&s.sc[ci0 + a][co0 + 4]) = s1;
                }
            }
            NB_SYNC(BAR_CONS, 128);

            // ---- softmax over j (4 warps x 16 rows) ----
#pragma unroll 2
            for (int r = 0; r < 16; r++) {
                int row = cw * 16 + r;
                float v0 = s.sc[row][lane], v1 = s.sc[row][lane + 32];
                float m = fmaxf(v0, v1);
#pragma unroll
                for (int d2 = 16; d2 > 0; d2 >>= 1)
                    m = fmaxf(m, __shfl_xor_sync(0xffffffffu, m, d2));
                float e0 = __expf(v0 - m), e1 = __expf(v1 - m);
                float ssum = e0 + e1;
#pragma unroll
                for (int d2 = 16; d2 > 0; d2 >>= 1)
                    ssum += __shfl_xor_sync(0xffffffffu, ssum, d2);
                float inv = 1.0f / ssum;
                s.sc[row][lane]      = e0 * inv;
                s.sc[row][lane + 32] = e1 * inv;
            }
            NB_SYNC(BAR_CONS, 128);

            // ---- out_h = alpha @ v + ew (ecoef == 1) ----
#pragma unroll 4
            for (int j = 0; j < Nn; j++) {
                ulonglong2 v0 = *reinterpret_cast<const ulonglong2*>(&s.vs[p][j][co0]);
                ulonglong2 v1 = *reinterpret_cast<const ulonglong2*>(&s.vs[p][j][co0 + 4]);
#pragma unroll
                for (int a = 0; a < 4; a++) {
                    ull ap = pack2(s.sc[ci0 + a][j]);
                    hacc[a][0] = fma2(ap, v0.x, hacc[a][0]);
                    hacc[a][1] = fma2(ap, v0.y, hacc[a][1]);
                    hacc[a][2] = fma2(ap, v1.x, hacc[a][2]);
                    hacc[a][3] = fma2(ap, v1.y, hacc[a][3]);
                }
            }
            {
                float4 e0 = *reinterpret_cast<const float4*>(&We[h * On + co0]);
                float4 e1 = *reinterpret_cast<const float4*>(&We[h * On + co0 + 4]);
                ull ew0 = packxy(e0.x, e0.y), ew1 = packxy(e0.z, e0.w);
                ull ew2 = packxy(e1.x, e1.y), ew3 = packxy(e1.z, e1.w);
#pragma unroll
                for (int a = 0; a < 4; a++) {
                    hacc[a][0] = fma2(ONE, ew0, hacc[a][0]);
                    hacc[a][1] = fma2(ONE, ew1, hacc[a][1]);
                    hacc[a][2] = fma2(ONE, ew2, hacc[a][2]);
                    hacc[a][3] = fma2(ONE, ew3, hacc[a][3]);
                }
            }
            NB_ARRIVE(BAR_FREE0 + p, THREADS);
        }

        // ---- final: mean heads + skip + bias, threshold, sigmoid, store ----
        {
            float4 bs0 = *reinterpret_cast<const float4*>(&bs[co0]);
            float4 bs1 = *reinterpret_cast<const float4*>(&bs[co0 + 4]);
            const float bb[8] = {bs0.x, bs0.y, bs0.z, bs0.w, bs1.x, bs1.y, bs1.z, bs1.w};
            float* og = outg + (size_t)b * Nn * On;
#pragma unroll
            for (int a = 0; a < 4; a++) {
                float z[8];
#pragma unroll
                for (int u = 0; u < 4; u++) {
                    float2 hv = unpack2(hacc[a][u]);
                    float2 sv = unpack2(skacc[a][u]);
                    z[2 * u]     = sv.x + hv.x * 0.125f + bb[2 * u];
                    z[2 * u + 1] = sv.y + hv.y * 0.125f + bb[2 * u + 1];
                }
                float4 r0, r1;
                r0.x = (z[0] > 0.1f) ? 1.0f / (1.0f + __expf(-z[0])) : 0.0f;
                r0.y = (z[1] > 0.1f) ? 1.0f / (1.0f + __expf(-z[1])) : 0.0f;
                r0.z = (z[2] > 0.1f) ? 1.0f / (1.0f + __expf(-z[2])) : 0.0f;
                r0.w = (z[3] > 0.1f) ? 1.0f / (1.0f + __expf(-z[3])) : 0.0f;
                r1.x = (z[4] > 0.1f) ? 1.0f / (1.0f + __expf(-z[4])) : 0.0f;
                r1.y = (z[5] > 0.1f) ? 1.0f / (1.0f + __expf(-z[5])) : 0.0f;
                r1.z = (z[6] > 0.1f) ? 1.0f / (1.0f + __expf(-z[6])) : 0.0f;
                r1.w = (z[7] > 0.1f) ? 1.0f / (1.0f + __expf(-z[7])) : 0.0f;
                *reinterpret_cast<float4*>(og + (ci0 + a) * On + co0)     = r0;
                *reinterpret_cast<float4*>(og + (ci0 + a) * On + co0 + 4) = r1;
            }
        }
    }
}

extern "C" void kernel_launch(void* const* d_in, const int* in_sizes, int n_in,
                              void* d_out, int out_size) {
    (void)in_sizes; (void)n_in; (void)out_size;
    const float* ctx = (const float*)d_in[0];
    const float* Wq  = (const float*)d_in[2];
    const float* bq  = (const float*)d_in[3];
    const float* Wk  = (const float*)d_in[4];
    const float* bk  = (const float*)d_in[5];
    const float* Wv  = (const float*)d_in[6];
    const float* bv  = (const float*)d_in[7];
    const float* We  = (const float*)d_in[8];
    const float* Ws  = (const float*)d_in[9];
    const float* bs  = (const float*)d_in[10];
    float* outg = (float*)d_out;

    transpose_weights_kernel<<<(Cn * HOn + 255) / 256, 256>>>(Wq, Wk, Wv, Ws);

    cudaFuncSetAttribute(graph_attn_kernel,
                         cudaFuncAttributeMaxDynamicSharedMemorySize,
                         (int)sizeof(Smem));

    graph_attn_kernel<<<Bn, THREADS, sizeof(Smem)>>>(ctx, bq, bk, bv, We, bs, outg);
}

// round 10
// speedup vs baseline: 1.1325x; 1.1325x over previous
#include <cuda_runtime.h>
#include <cstdint>

#define Bn 1024
#define Nn 64
#define Cn 256
#define Hn 8
#define On 64
#define HOn 512

#define THREADS 384
#define NPROD 256
#define NCONS 128
#define XS_STRIDE 260
#define TS 68
#define CK 16                  // K-chunk for staged weights
#define CHUNKS_PER_HEAD (Cn / CK)          // 16
#define TOTAL_UNITS (Hn * CHUNKS_PER_HEAD) // 128

// named barrier ids
#define BAR_READY0 1   // +p : producers arrive, consumers sync (384)
#define BAR_FREE0  3   // +p : consumers arrive, producers sync (384)
#define BAR_PROD   5   // producers only (256)
#define BAR_CONS   6   // consumers only (128)

#define NB_SYNC(id, cnt)   asm volatile("bar.sync %0, %1;"   :: "r"(id), "r"(cnt) : "memory")
#define NB_ARRIVE(id, cnt) asm volatile("bar.arrive %0, %1;" :: "r"(id), "r"(cnt) : "memory")

typedef unsigned long long ull;

// ---------- f32x2 packed-FMA helpers ----------
__device__ __forceinline__ ull fma2(ull a, ull b, ull c) {
    ull d;
    asm("fma.rn.f32x2 %0, %1, %2, %3;" : "=l"(d) : "l"(a), "l"(b), "l"(c));
    return d;
}
__device__ __forceinline__ ull pack2(float x) {
    ull d;
    asm("mov.b64 %0, {%1, %1};" : "=l"(d) : "f"(x));
    return d;
}
__device__ __forceinline__ ull packxy(float x, float y) {
    ull d;
    asm("mov.b64 %0, {%1, %2};" : "=l"(d) : "f"(x), "f"(y));
    return d;
}
__device__ __forceinline__ float2 unpack2(ull v) {
    float2 r;
    asm("mov.b64 {%0, %1}, %2;" : "=f"(r.x), "=f"(r.y) : "l"(v));
    return r;
}

// ---------- transposed-weight scratch ----------
__device__ __align__(16) float g_WqT[Cn * HOn];
__device__ __align__(16) float g_WkT[Cn * HOn];
__device__ __align__(16) float g_WvT[Cn * HOn];
__device__ __align__(16) float g_WsT[Cn * On];

__global__ void transpose_weights_kernel(const float* __restrict__ Wq,
                                         const float* __restrict__ Wk,
                                         const float* __restrict__ Wv,
                                         const float* __restrict__ Ws) {
    int idx = blockIdx.x * 256 + threadIdx.x;
    if (idx < Cn * HOn) {
        int c = idx / HOn, ho = idx - c * HOn;
        g_WqT[idx] = Wq[ho * Cn + c];
        g_WkT[idx] = Wk[ho * Cn + c];
        g_WvT[idx] = Wv[ho * Cn + c];
    }
    if (idx < Cn * On) {
        int c = idx / On, o = idx - c * On;
        g_WsT[idx] = Ws[o * Cn + c];
    }
}

// ---------- shared-memory layout ----------
struct __align__(16) Smem {
    float xs[Nn][XS_STRIDE];      // x row-major [i][c]                (~65KB)
    float qs[2][Nn][TS];          // q row-major [i][o], double-buffered
    float kT[2][Nn][TS];          // k transposed [o][j]
    float vs[2][Nn][TS];          // v row-major [j][o]                (102KB)
    float sc[Nn][TS];             // consumer scratch: scores -> alpha (17KB)
    float wbuf[2][3][CK][On];     // double-buffered weight chunk Q/K/V (24KB)
};

__device__ __forceinline__ uint32_t smem_addr_of(const void* p) {
    uint32_t a;
    asm("{ .reg .u64 t; cvta.to.shared.u64 t, %1; cvt.u32.u64 %0, t; }"
        : "=r"(a) : "l"(p));
    return a;
}

// Stage one chunk (all 3 mats, CK x 64 each) for (head h, chunk kc) into wbuf[buf].
// 3*16*64 floats = 768 float4; 256 producer threads x 3.
__device__ __forceinline__ void stage_chunk(Smem& s, int buf, int h, int kc, int tp) {
    const int c0 = kc * CK;
#pragma unroll
    for (int i = 0; i < 3; i++) {
        int p = tp + i * NPROD;          // 0..767
        int m = p >> 8;                  // matrix 0..2
        int rem = p & 255;
        int kl = rem >> 4, c4 = rem & 15;
        const float* base = (m == 0) ? g_WqT : (m == 1) ? g_WkT : g_WvT;
        const float* src = base + (size_t)(c0 + kl) * HOn + h * On + c4 * 4;
        uint32_t sa = smem_addr_of(&s.wbuf[buf][m][kl][c4 * 4]);
        asm volatile("cp.async.cg.shared.global [%0], [%1], 16;" :: "r"(sa), "l"(src));
    }
    asm volatile("cp.async.commit_group;");
}
#define CP_WAIT0() asm volatile("cp.async.wait_group 0;" ::: "memory")

// consumer skip GEMM: 4 rows x 8 cols tile, weights via LDG (once per CTA)
__device__ __forceinline__ void gemm48(const float* __restrict__ xrow,
                                       const float* __restrict__ wcol,
                                       ull acc[4][4]) {
#pragma unroll
    for (int a = 0; a < 4; a++)
#pragma unroll
        for (int u = 0; u < 4; u++) acc[a][u] = 0ull;
#pragma unroll 2
    for (int c4 = 0; c4 < Cn / 4; c4++) {
        float4 xv[4];
#pragma unroll
        for (int a = 0; a < 4; a++)
            xv[a] = *reinterpret_cast<const float4*>(xrow + a * XS_STRIDE + c4 * 4);
        ulonglong2 wv[4][2];
#pragma unroll
        for (int cc = 0; cc < 4; cc++) {
            const float* wp = wcol + (c4 * 4 + cc) * On;
            wv[cc][0] = *reinterpret_cast<const ulonglong2*>(wp);
            wv[cc][1] = *reinterpret_cast<const ulonglong2*>(wp + 4);
        }
#pragma unroll
        for (int cc = 0; cc < 4; cc++) {
#pragma unroll
            for (int a = 0; a < 4; a++) {
                ull xp = pack2(reinterpret_cast<const float*>(&xv[a])[cc]);
                acc[a][0] = fma2(xp, wv[cc][0].x, acc[a][0]);
                acc[a][1] = fma2(xp, wv[cc][0].y, acc[a][1]);
                acc[a][2] = fma2(xp, wv[cc][1].x, acc[a][2]);
                acc[a][3] = fma2(xp, wv[cc][1].y, acc[a][3]);
            }
        }
    }
}

__global__ void __launch_bounds__(THREADS, 1)
graph_attn_kernel(const float* __restrict__ ctx,
                  const float* __restrict__ bq, const float* __restrict__ bk,
                  const float* __restrict__ bv, const float* __restrict__ We,
                  const float* __restrict__ bs, float* __restrict__ outg) {
    extern __shared__ char smem_raw[];
    Smem& s = *reinterpret_cast<Smem*>(smem_raw);

    const int b = blockIdx.x;
    const int tid = (int)threadIdx.x;
    const bool is_prod = tid < NPROD;

    // ---- producers prefetch head-0 chunk-0 weights before x load ----
    if (is_prod) stage_chunk(s, 0, 0, 0, tid);

    // ---- all threads load x (64x256) into SMEM ----
    {
        const float4* xg = reinterpret_cast<const float4*>(ctx + (size_t)b * Nn * Cn);
        for (int p = tid; p < 4096; p += THREADS) {
            int i = p >> 6, c4 = p & 63;
            *reinterpret_cast<float4*>(&s.xs[i][c4 * 4]) = xg[p];
        }
    }
    if (is_prod) CP_WAIT0();
    __syncthreads();

    if (is_prod) {
        // ======================= PRODUCER (warps 0-7) =======================
        // 4 rows x 4 cols per thread, all three mats fused (shared x loads).
        const int ti = tid >> 4, to = tid & 15;
        const int i0 = ti * 4, o0 = to * 4;

        for (int h = 0; h < Hn; h++) {
            const int p = h & 1;
            if (h >= 2) NB_SYNC(BAR_FREE0 + p, THREADS);

            ull acc[3][4][2];
#pragma unroll
            for (int m = 0; m < 3; m++)
#pragma unroll
                for (int a = 0; a < 4; a++) { acc[m][a][0] = 0ull; acc[m][a][1] = 0ull; }

#pragma unroll 1
            for (int kc = 0; kc < CHUNKS_PER_HEAD; kc++) {
                const int gu = h * CHUNKS_PER_HEAD + kc;
                const int ngu = gu + 1;
                if (ngu < TOTAL_UNITS)
                    stage_chunk(s, ngu & 1, ngu >> 4, ngu & 15, tid);

                const float(*wb)[CK][On] = s.wbuf[gu & 1];
                const float* xb = &s.xs[i0][kc * CK];
#pragma unroll
                for (int c4 = 0; c4 < CK / 4; c4++) {
                    float4 xv[4];
#pragma unroll
                    for (int a = 0; a < 4; a++)
                        xv[a] = *reinterpret_cast<const float4*>(
                            xb + a * XS_STRIDE + c4 * 4);
#pragma unroll
                    for (int cc = 0; cc < 4; cc++) {
                        ulonglong2 wq = *reinterpret_cast<const ulonglong2*>(&wb[0][c4 * 4 + cc][o0]);
                        ulonglong2 wk = *reinterpret_cast<const ulonglong2*>(&wb[1][c4 * 4 + cc][o0]);
                        ulonglong2 wv = *reinterpret_cast<const ulonglong2*>(&wb[2][c4 * 4 + cc][o0]);
#pragma unroll
                        for (int a = 0; a < 4; a++) {
                            ull xp = pack2(reinterpret_cast<const float*>(&xv[a])[cc]);
                            acc[0][a][0] = fma2(xp, wq.x, acc[0][a][0]);
                            acc[0][a][1] = fma2(xp, wq.y, acc[0][a][1]);
                            acc[1][a][0] = fma2(xp, wk.x, acc[1][a][0]);
                            acc[1][a][1] = fma2(xp, wk.y, acc[1][a][1]);
                            acc[2][a][0] = fma2(xp, wv.x, acc[2][a][0]);
                            acc[2][a][1] = fma2(xp, wv.y, acc[2][a][1]);
                        }
                    }
                }
                CP_WAIT0();
                NB_SYNC(BAR_PROD, NPROD);
            }

            // ---- epilogues: Q row-major, K transposed, V row-major ----
            {
                float4 b4 = *reinterpret_cast<const float4*>(&bq[h * On + o0]);
#pragma unroll
                for (int a = 0; a < 4; a++) {
                    float2 r0 = unpack2(acc[0][a][0]), r1 = unpack2(acc[0][a][1]);
                    float4 q = {r0.x + b4.x, r0.y + b4.y, r1.x + b4.z, r1.y + b4.w};
                    *reinterpret_cast<float4*>(&s.qs[p][i0 + a][o0]) = q;
                }
            }
            {
                float4 b4 = *reinterpret_cast<const float4*>(&bk[h * On + o0]);
                const float bb[4] = {b4.x, b4.y, b4.z, b4.w};
#pragma unroll
                for (int a = 0; a < 4; a++) {
                    float v[4];
                    float2 r0 = unpack2(acc[1][a][0]), r1 = unpack2(acc[1][a][1]);
                    v[0] = r0.x; v[1] = r0.y; v[2] = r1.x; v[3] = r1.y;
#pragma unroll
                    for (int c = 0; c < 4; c++)
                        s.kT[p][o0 + c][i0 + a] = v[c] + bb[c];
                }
            }
            {
                float4 b4 = *reinterpret_cast<const float4*>(&bv[h * On + o0]);
#pragma unroll
                for (int a = 0; a < 4; a++) {
                    float2 r0 = unpack2(acc[2][a][0]), r1 = unpack2(acc[2][a][1]);
                    float4 v = {r0.x + b4.x, r0.y + b4.y, r1.x + b4.z, r1.y + b4.w};
                    *reinterpret_cast<float4*>(&s.vs[p][i0 + a][o0]) = v;
                }
            }
            NB_ARRIVE(BAR_READY0 + p, THREADS);
        }
    } else {
        // ======================= CONSUMER (warps 8-11) =======================
        const int ct = tid - NPROD;            // 0..127
        const int it = ct >> 3, jt = ct & 7;
        const int ci0 = it * 4, co0 = jt * 8;  // 4 rows x 8 cols
        const int cw = ct >> 5, lane = ct & 31;

        // skip GEMM (overlaps head-0 projections)
        ull skacc[4][4];
        gemm48(&s.xs[ci0][0], g_WsT + co0, skacc);

        // head-sum accumulator
        ull hacc[4][4];
#pragma unroll
        for (int a = 0; a < 4; a++)
#pragma unroll
            for (int u = 0; u < 4; u++) hacc[a][u] = 0ull;

        const ull ONE = pack2(1.0f);

        for (int h = 0; h < Hn; h++) {
            const int p = h & 1;
            NB_SYNC(BAR_READY0 + p, THREADS);

            // ---- scores = q k^T / 8 (adj==1: qe term softmax-invariant) ----
            {
                ull sacc[4][4];
#pragma unroll
                for (int a = 0; a < 4; a++)
#pragma unroll
                    for (int u = 0; u < 4; u++) sacc[a][u] = 0ull;
#pragma unroll 4
                for (int o = 0; o < Nn; o++) {
                    ulonglong2 k0 = *reinterpret_cast<const ulonglong2*>(&s.kT[p][o][co0]);
                    ulonglong2 k1 = *reinterpret_cast<const ulonglong2*>(&s.kT[p][o][co0 + 4]);
#pragma unroll
                    for (int a = 0; a < 4; a++) {
                        ull qp = pack2(s.qs[p][ci0 + a][o]);
                        sacc[a][0] = fma2(qp, k0.x, sacc[a][0]);
                        sacc[a][1] = fma2(qp, k0.y, sacc[a][1]);
                        sacc[a][2] = fma2(qp, k1.x, sacc[a][2]);
                        sacc[a][3] = fma2(qp, k1.y, sacc[a][3]);
                    }
                }
#pragma unroll
                for (int a = 0; a < 4; a++) {
                    float2 r0 = unpack2(sacc[a][0]), r1 = unpack2(sacc[a][1]);
                    float2 r2 = unpack2(sacc[a][2]), r3 = unpack2(sacc[a][3]);
                    float4 s0 = {r0.x * 0.125f, r0.y * 0.125f, r1.x * 0.125f, r1.y * 0.125f};
                    float4 s1 = {r2.x * 0.125f, r2.y * 0.125f, r3.x * 0.125f, r3.y * 0.125f};
                    *reinterpret_cast<float4*>(&s.sc[ci0 + a][co0]) = s0;
                    *reinterpret_cast<float4*>(&s.sc[ci0 + a][co0 + 4]) = s1;
                }
            }
            NB_SYNC(BAR_CONS, NCONS);

            // ---- softmax over j (4 warps x 16 rows) ----
#pragma unroll 2
            for (int r = 0; r < 16; r++) {
                int row = cw * 16 + r;
                float v0 = s.sc[row][lane], v1 = s.sc[row][lane + 32];
                float m = fmaxf(v0, v1);
#pragma unroll
                for (int d2 = 16; d2 > 0; d2 >>= 1)
                    m = fmaxf(m, __shfl_xor_sync(0xffffffffu, m, d2));
                float e0 = __expf(v0 - m), e1 = __expf(v1 - m);
                float ssum = e0 + e1;
#pragma unroll
                for (int d2 = 16; d2 > 0; d2 >>= 1)
                    ssum += __shfl_xor_sync(0xffffffffu, ssum, d2);
                float inv = 1.0f / ssum;
                s.sc[row][lane]      = e0 * inv;
                s.sc[row][lane + 32] = e1 * inv;
            }
            NB_SYNC(BAR_CONS, NCONS);

            // ---- out_h = alpha @ v + ew (ecoef == 1) ----
#pragma unroll 4
            for (int j = 0; j < Nn; j++) {
                ulonglong2 v0 = *reinterpret_cast<const ulonglong2*>(&s.vs[p][j][co0]);
                ulonglong2 v1 = *reinterpret_cast<const ulonglong2*>(&s.vs[p][j][co0 + 4]);
#pragma unroll
                for (int a = 0; a < 4; a++) {
                    ull ap = pack2(s.sc[ci0 + a][j]);
                    hacc[a][0] = fma2(ap, v0.x, hacc[a][0]);
                    hacc[a][1] = fma2(ap, v0.y, hacc[a][1]);
                    hacc[a][2] = fma2(ap, v1.x, hacc[a][2]);
                    hacc[a][3] = fma2(ap, v1.y, hacc[a][3]);
                }
            }
            {
                float4 e0 = *reinterpret_cast<const float4*>(&We[h * On + co0]);
                float4 e1 = *reinterpret_cast<const float4*>(&We[h * On + co0 + 4]);
                ull ew0 = packxy(e0.x, e0.y), ew1 = packxy(e0.z, e0.w);
                ull ew2 = packxy(e1.x, e1.y), ew3 = packxy(e1.z, e1.w);
#pragma unroll
                for (int a = 0; a < 4; a++) {
                    hacc[a][0] = fma2(ONE, ew0, hacc[a][0]);
                    hacc[a][1] = fma2(ONE, ew1, hacc[a][1]);
                    hacc[a][2] = fma2(ONE, ew2, hacc[a][2]);
                    hacc[a][3] = fma2(ONE, ew3, hacc[a][3]);
                }
            }
            NB_ARRIVE(BAR_FREE0 + p, THREADS);
        }

        // ---- final: mean heads + skip + bias, threshold, sigmoid, store ----
        {
            float4 bs0 = *reinterpret_cast<const float4*>(&bs[co0]);
            float4 bs1 = *reinterpret_cast<const float4*>(&bs[co0 + 4]);
            const float bb[8] = {bs0.x, bs0.y, bs0.z, bs0.w, bs1.x, bs1.y, bs1.z, bs1.w};
            float* og = outg + (size_t)b * Nn * On;
#pragma unroll
            for (int a = 0; a < 4; a++) {
                float z[8];
#pragma unroll
                for (int u = 0; u < 4; u++) {
                    float2 hv = unpack2(hacc[a][u]);
                    float2 sv = unpack2(skacc[a][u]);
                    z[2 * u]     = sv.x + hv.x * 0.125f + bb[2 * u];
                    z[2 * u + 1] = sv.y + hv.y * 0.125f + bb[2 * u + 1];
                }
                float4 r0, r1;
                r0.x = (z[0] > 0.1f) ? 1.0f / (1.0f + __expf(-z[0])) : 0.0f;
                r0.y = (z[1] > 0.1f) ? 1.0f / (1.0f + __expf(-z[1])) : 0.0f;
                r0.z = (z[2] > 0.1f) ? 1.0f / (1.0f + __expf(-z[2])) : 0.0f;
                r0.w = (z[3] > 0.1f) ? 1.0f / (1.0f + __expf(-z[3])) : 0.0f;
                r1.x = (z[4] > 0.1f) ? 1.0f / (1.0f + __expf(-z[4])) : 0.0f;
                r1.y = (z[5] > 0.1f) ? 1.0f / (1.0f + __expf(-z[5])) : 0.0f;
                r1.z = (z[6] > 0.1f) ? 1.0f / (1.0f + __expf(-z[6])) : 0.0f;
                r1.w = (z[7] > 0.1f) ? 1.0f / (1.0f + __expf(-z[7])) : 0.0f;
                *reinterpret_cast<float4*>(og + (ci0 + a) * On + co0)     = r0;
                *reinterpret_cast<float4*>(og + (ci0 + a) * On + co0 + 4) = r1;
            }
        }
    }
}

extern "C" void kernel_launch(void* const* d_in, const int* in_sizes, int n_in,
                              void* d_out, int out_size) {
    (void)in_sizes; (void)n_in; (void)out_size;
    const float* ctx = (const float*)d_in[0];
    const float* Wq  = (const float*)d_in[2];
    const float* bq  = (const float*)d_in[3];
    const float* Wk  = (const float*)d_in[4];
    const float* bk  = (const float*)d_in[5];
    const float* Wv  = (const float*)d_in[6];
    const float* bv  = (const float*)d_in[7];
    const float* We  = (const float*)d_in[8];
    const float* Ws  = (const float*)d_in[9];
    const float* bs  = (const float*)d_in[10];
    float* outg = (float*)d_out;

    transpose_weights_kernel<<<(Cn * HOn + 255) / 256, 256>>>(Wq, Wk, Wv, Ws);

    cudaFuncSetAttribute(graph_attn_kernel,
                         cudaFuncAttributeMaxDynamicSharedMemorySize,
                         (int)sizeof(Smem));

    graph_attn_kernel<<<Bn, THREADS, sizeof(Smem)>>>(ctx, bq, bk, bv, We, bs, outg);
}